// round 15
// baseline (speedup 1.0000x reference)
#include <cuda_runtime.h>
#include <cuda_fp16.h>
#include <cuda_bf16.h>

// Problem constants
#define NNODES 50000
#define NEDGES 800000
#define IN_DIM 256
#define HDIM   128
#define H2DIM  64
#define ODIM   32
#define KHOPS  5
#define EPS    1e-5f

#define GEMM_BLOCKS ((NNODES + 63) / 64)   // 782
#define WS_BLOCKS   160                    // extra blocks in K1 for wsum/deg
#define PADCAP      (NEDGES + 8 * NNODES + 16)  // padded edge capacity (+prefetch overrun)

// ---------------------------------------------------------------------------
// Scratch (device globals; zero-initialized at module load).
// gWsum/gDeg re-zeroed at END of every launch (head_kernel) for graph replay.
// ---------------------------------------------------------------------------
__device__ float    gB1[NNODES * HDIM];    // GEMM1 output
__device__ float    gFz[NNODES * HDIM];    // fused accumulator
__device__ __half   gH0[NNODES * HDIM];    // fp16 state buffers (rotating)
__device__ __half   gH1[NNODES * HDIM];
__device__ __half   gH2[NNODES * HDIM];
__device__ float    gWsum[NNODES];
__device__ int      gDeg[NNODES];
__device__ int      gCur[NNODES];
__device__ int      gOff[NNODES + 1];
__device__ unsigned gEdge[PADCAP];         // {u16 src | fp16 weight << 16}
__device__ float    gSw[8];

// ---------------------------------------------------------------------------
// PDL primitives
// ---------------------------------------------------------------------------
__device__ __forceinline__ void pdl_wait()   { asm volatile("griddepcontrol.wait;" ::: "memory"); }
__device__ __forceinline__ void pdl_launch() { asm volatile("griddepcontrol.launch_dependents;"); }

// ---------------------------------------------------------------------------
// tf32 mma.sync m16n8k8 (fp32 bits passed directly; HW truncates to tf32)
// ---------------------------------------------------------------------------
__device__ __forceinline__ void mma_tf32(float* d, const float* a, const float* b) {
    asm volatile(
        "mma.sync.aligned.m16n8k8.row.col.f32.tf32.tf32.f32 "
        "{%0,%1,%2,%3}, {%4,%5,%6,%7}, {%8,%9}, {%0,%1,%2,%3};\n"
        : "+f"(d[0]), "+f"(d[1]), "+f"(d[2]), "+f"(d[3])
        : "r"(__float_as_uint(a[0])), "r"(__float_as_uint(a[1])),
          "r"(__float_as_uint(a[2])), "r"(__float_as_uint(a[3])),
          "r"(__float_as_uint(b[0])), "r"(__float_as_uint(b[1])));
}

// ---------------------------------------------------------------------------
// Tensor-core GEMM body: 64x128 block tile, 8 warps in 2x4 grid, 32x32/warp.
// Register-staged double buffering.
// ---------------------------------------------------------------------------
template <int KDIM, bool RES, bool FUSEP>
__device__ __forceinline__ void gemm_body(
    int bx,
    const float* __restrict__ A,
    const float* __restrict__ W,
    const float* __restrict__ bias,
    const float* __restrict__ g,
    const float* __restrict__ be,
    const float* __restrict__ m,
    const float* __restrict__ v,
    const float* __restrict__ ident,
    float* __restrict__ out32,
    __half* __restrict__ out16,
    float* __restrict__ F,
    const float* __restrict__ sw, int M) {
    __shared__ float As[64][17];
    __shared__ float Bs[16][136];
    __shared__ float sS[HDIM], sSh[HDIM], sBB[HDIM];

    const int tid = threadIdx.x;
    const int rowBase = bx * 64;
    const int wid = tid >> 5, lane = tid & 31;
    const int warpM = wid >> 2, warpN = wid & 3;
    const int gg = lane >> 2, tig = lane & 3;

    if (tid < HDIM) {
        float s = g[tid] * rsqrtf(v[tid] + EPS);
        sS[tid] = s;
        sSh[tid] = be[tid] - m[tid] * s;
        sBB[tid] = bias[tid];
    }

    float acc[2][4][4];
#pragma unroll
    for (int mt = 0; mt < 2; mt++)
#pragma unroll
        for (int nt = 0; nt < 4; nt++)
#pragma unroll
            for (int j = 0; j < 4; j++) acc[mt][nt][j] = 0.f;

    const int ar = tid >> 2, ac4 = tid & 3;
    const int wr0 = tid >> 5, wc0 = tid & 31;
    const int wr1 = (tid + 256) >> 5, wc1 = tid & 31;
    float4 nA, nW0, nW1;

    nA = make_float4(0.f, 0.f, 0.f, 0.f);
    if (rowBase + ar < M)
        nA = *(const float4*)(A + (size_t)(rowBase + ar) * KDIM + ac4 * 4);
    nW0 = *(const float4*)(W + (size_t)wr0 * HDIM + wc0 * 4);
    nW1 = *(const float4*)(W + (size_t)wr1 * HDIM + wc1 * 4);

    for (int k0 = 0; k0 < KDIM; k0 += 16) {
        As[ar][ac4 * 4 + 0] = nA.x; As[ar][ac4 * 4 + 1] = nA.y;
        As[ar][ac4 * 4 + 2] = nA.z; As[ar][ac4 * 4 + 3] = nA.w;
        *(float4*)&Bs[wr0][wc0 * 4] = nW0;
        *(float4*)&Bs[wr1][wc1 * 4] = nW1;
        __syncthreads();

        if (k0 + 16 < KDIM) {
            nA = make_float4(0.f, 0.f, 0.f, 0.f);
            if (rowBase + ar < M)
                nA = *(const float4*)(A + (size_t)(rowBase + ar) * KDIM + (k0 + 16) + ac4 * 4);
            nW0 = *(const float4*)(W + (size_t)(k0 + 16 + wr0) * HDIM + wc0 * 4);
            nW1 = *(const float4*)(W + (size_t)(k0 + 16 + wr1) * HDIM + wc1 * 4);
        }

#pragma unroll
        for (int kk = 0; kk < 16; kk += 8) {
            float afr[2][4], bfr[4][2];
#pragma unroll
            for (int mt = 0; mt < 2; mt++) {
                int r0 = warpM * 32 + mt * 16 + gg;
                afr[mt][0] = As[r0][kk + tig];
                afr[mt][1] = As[r0 + 8][kk + tig];
                afr[mt][2] = As[r0][kk + tig + 4];
                afr[mt][3] = As[r0 + 8][kk + tig + 4];
            }
#pragma unroll
            for (int nt = 0; nt < 4; nt++) {
                int c0 = warpN * 32 + nt * 8 + gg;
                bfr[nt][0] = Bs[kk + tig][c0];
                bfr[nt][1] = Bs[kk + tig + 4][c0];
            }
#pragma unroll
            for (int mt = 0; mt < 2; mt++)
#pragma unroll
                for (int nt = 0; nt < 4; nt++)
                    mma_tf32(acc[mt][nt], afr[mt], bfr[nt]);
        }
        __syncthreads();
    }

    float fw = FUSEP ? __ldg(sw) : 0.f;

#pragma unroll
    for (int mt = 0; mt < 2; mt++) {
#pragma unroll
        for (int half = 0; half < 2; half++) {
            int rr = rowBase + warpM * 32 + mt * 16 + gg + half * 8;
            if (rr < M) {
#pragma unroll
                for (int nt = 0; nt < 4; nt++) {
                    int c = warpN * 32 + nt * 8 + 2 * tig;
                    float d0 = acc[mt][nt][half * 2 + 0];
                    float d1 = acc[mt][nt][half * 2 + 1];
                    float o0 = fmaxf((d0 + sBB[c]) * sS[c] + sSh[c], 0.f);
                    float o1 = fmaxf((d1 + sBB[c + 1]) * sS[c + 1] + sSh[c + 1], 0.f);
                    if (RES) {
                        float2 r4 = *(const float2*)(ident + (size_t)rr * HDIM + c);
                        o0 += r4.x; o1 += r4.y;
                    }
                    if (FUSEP) {
                        __half2 h = __floats2half2_rn(o0, o1);
                        *(unsigned*)(out16 + (size_t)rr * HDIM + c) = *(unsigned*)&h;
                        float2 f = make_float2(fw * o0, fw * o1);
                        *(float2*)(F + (size_t)rr * HDIM + c) = f;
                    } else {
                        *(float2*)(out32 + (size_t)rr * HDIM + c) = make_float2(o0, o1);
                    }
                }
            }
        }
    }
}

// ---------------------------------------------------------------------------
// K1: GEMM1 + (tail blocks) wsum/deg accumulation + softmax(att)
// ---------------------------------------------------------------------------
__global__ void k1_gemm1_wsum(const float* __restrict__ x,
                              const float* __restrict__ W1,
                              const float* __restrict__ b1,
                              const float* __restrict__ g1,
                              const float* __restrict__ be1,
                              const float* __restrict__ m1,
                              const float* __restrict__ v1,
                              float* __restrict__ out32,
                              const int* __restrict__ row,
                              const int* __restrict__ col,
                              const float* __restrict__ ew,
                              float* __restrict__ ws,
                              int* __restrict__ deg,
                              const float* __restrict__ att,
                              float* __restrict__ sw) {
    int bx = blockIdx.x;
    if (bx < GEMM_BLOCKS) {
        gemm_body<IN_DIM, false, false>(bx, x, W1, b1, g1, be1, m1, v1,
                                        nullptr, out32, nullptr, nullptr, nullptr, NNODES);
        return;
    }
    int ebx = bx - GEMM_BLOCKS;
    for (int i = ebx * 256 + threadIdx.x; i < NEDGES; i += WS_BLOCKS * 256) {
        atomicAdd(&ws[row[i]], ew[i]);
        atomicAdd(&deg[col[i]], 1);
    }
    if (ebx == WS_BLOCKS - 1 && threadIdx.x == 0) {
        float mx = -1e30f;
        for (int i = 0; i < KHOPS + 1; i++) mx = fmaxf(mx, att[i]);
        float e[KHOPS + 1], sum = 0.f;
        for (int i = 0; i < KHOPS + 1; i++) { e[i] = expf(att[i] - mx); sum += e[i]; }
        for (int i = 0; i < KHOPS + 1; i++) sw[i] = e[i] / sum;
    }
}

// ---------------------------------------------------------------------------
// K2: GEMM2 (+ fp16 state + F init) + (1 tail block) PADDED offset scan
// ---------------------------------------------------------------------------
__global__ void k2_gemm2_scan(const float* __restrict__ h1,
                              const float* __restrict__ W2,
                              const float* __restrict__ b2,
                              const float* __restrict__ g2,
                              const float* __restrict__ be2,
                              const float* __restrict__ m2,
                              const float* __restrict__ v2,
                              __half* __restrict__ out16,
                              float* __restrict__ F,
                              const float* __restrict__ sw,
                              const int* __restrict__ deg,
                              int* __restrict__ off,
                              int* __restrict__ cursor) {
    int bx = blockIdx.x;
    if (bx < GEMM_BLOCKS) {
        gemm_body<HDIM, true, true>(bx, h1, W2, b2, g2, be2, m2, v2,
                                    h1, nullptr, out16, F, sw, NNODES);
        return;
    }
    __shared__ int partial[256];
    const int CH = (NNODES + 255) / 256;   // 196
    int tid = threadIdx.x;
    int start = tid * CH;
    int sum = 0;
    for (int j = 0; j < CH; j++) {
        int idx = start + j;
        if (idx < NNODES) sum += (deg[idx] + 7) & ~7;
    }
    partial[tid] = sum;
    __syncthreads();
    for (int d = 1; d < 256; d <<= 1) {
        int t = (tid >= d) ? partial[tid - d] : 0;
        __syncthreads();
        partial[tid] += t;
        __syncthreads();
    }
    int run = (tid == 0) ? 0 : partial[tid - 1];
    for (int j = 0; j < CH; j++) {
        int idx = start + j;
        if (idx < NNODES) {
            off[idx] = run;
            cursor[idx] = run;
            run += (deg[idx] + 7) & ~7;
        }
    }
    if (tid == 255) off[NNODES] = partial[255];
}

// ---------------------------------------------------------------------------
// K3: fill CSC (edge blocks) + pad fill (node tail blocks).
// Record: bits[0:16) = src node id, bits[16:32) = fp16 normalized weight.
// ---------------------------------------------------------------------------
#define EDGE_BLOCKS ((NEDGES + 255) / 256)
#define NODE_BLOCKS ((NNODES + 255) / 256)

__global__ void fill_csc_pad(const int* __restrict__ row,
                             const int* __restrict__ col,
                             const float* __restrict__ w,
                             const float* __restrict__ ws,
                             const int* __restrict__ deg,
                             const int* __restrict__ off,
                             int* __restrict__ cursor,
                             unsigned* __restrict__ edge) {
    int bx = blockIdx.x;
    if (bx < EDGE_BLOCKS) {
        int i = bx * 256 + threadIdx.x;
        if (i < NEDGES) {
            int r = row[i];
            int c = col[i];
            float wn = 0.9f * w[i] / fmaxf(ws[r], 1.0f);
            unsigned hw = (unsigned)__half_as_ushort(__float2half_rn(wn));
            int pos = atomicAdd(&cursor[c], 1);
            edge[pos] = (unsigned)r | (hw << 16);
        }
        return;
    }
    int n = (bx - EDGE_BLOCKS) * 256 + threadIdx.x;
    if (n < NNODES) {
        int d = deg[n];
        int s = off[n] + d;
        int e = off[n] + ((d + 7) & ~7);
        for (int p = s; p < e; p++) edge[p] = 0u;   // src 0, weight 0
    }
}

// ---------------------------------------------------------------------------
// Propagation gather — half-warp owns 4 contiguous edges per trip (one
// LDG.128 fetches all 4 records), LDG.128 rows, padded, HFMA2 inner math
// with per-trip fp32 flush (<=4 fp16 adds per partial), PRMT decode,
// unclamped next-trip prefetch, PDL pre-sync edge/offset loading.
// ---------------------------------------------------------------------------
// (u & 0xFFFF) << 8 as a single PRMT
__device__ __forceinline__ unsigned addr8(unsigned u) { return __byte_perm(u, 0, 0x4104); }
// duplicate high 16 bits into both halves: half2(w, w) in one PRMT
__device__ __forceinline__ __half2 wdup(unsigned u) {
    unsigned d = __byte_perm(u, u, 0x3232);
    return *(__half2*)&d;
}

// h[0..3] += half2(rows of p) * w2   (4 HFMA2)
__device__ __forceinline__ void hacc4(__half2* h, uint4 p, __half2 w2) {
    h[0] = __hfma2(*(__half2*)&p.x, w2, h[0]);
    h[1] = __hfma2(*(__half2*)&p.y, w2, h[1]);
    h[2] = __hfma2(*(__half2*)&p.z, w2, h[2]);
    h[3] = __hfma2(*(__half2*)&p.w, w2, h[3]);
}

template <bool FIN, bool WRITE>
__global__ void __launch_bounds__(256, 6)
prop_gather_h(const __half* __restrict__ src16,
              const __half* __restrict__ anc16,
              __half* __restrict__ dst16,
              const int* __restrict__ off,
              const unsigned* __restrict__ edge,
              float* __restrict__ F,
              const float* __restrict__ sw, int swIdx) {
    int warp = (blockIdx.x * blockDim.x + threadIdx.x) >> 5;
    int lane = threadIdx.x & 31;
    int halfe = lane >> 4;    // which 4-edge group of the trip
    int hl    = lane & 15;    // feature chunk within the row (8 fp16)

    // ---- pre-sync: offsets + first edge records (stable across steps) ----
    int s = 0, e = 0;
    uint4 er = make_uint4(0u, 0u, 0u, 0u);
    if (warp < NNODES) {
        s = __ldg(off + warp);
        e = __ldg(off + warp + 1);   // e - s multiple of 8
        er = __ldg((const uint4*)(edge + s + halfe * 4));
    }

    pdl_wait();
    pdl_launch();

    if (warp >= NNODES) return;

    const char* rowBase = (const char*)src16 + (hl << 4);

    float a[8];
#pragma unroll
    for (int j = 0; j < 8; j++) a[j] = 0.f;

    for (int i = s + halfe * 4; i < e; ) {
        uint4 en = __ldg((const uint4*)(edge + i + 8));  // unclamped (padded)

        uint4 p0 = __ldg((const uint4*)(rowBase + addr8(er.x)));
        uint4 p1 = __ldg((const uint4*)(rowBase + addr8(er.y)));
        uint4 p2 = __ldg((const uint4*)(rowBase + addr8(er.z)));
        uint4 p3 = __ldg((const uint4*)(rowBase + addr8(er.w)));

        __half2 h[4];
        h[0] = __hmul2(*(__half2*)&p0.x, wdup(er.x));
        h[1] = __hmul2(*(__half2*)&p0.y, wdup(er.x));
        h[2] = __hmul2(*(__half2*)&p0.z, wdup(er.x));
        h[3] = __hmul2(*(__half2*)&p0.w, wdup(er.x));
        hacc4(h, p1, wdup(er.y));
        hacc4(h, p2, wdup(er.z));
        hacc4(h, p3, wdup(er.w));

        // flush fp16 partials (<=4 products each) to fp32
        float2 f0 = __half22float2(h[0]);
        float2 f1 = __half22float2(h[1]);
        float2 f2 = __half22float2(h[2]);
        float2 f3 = __half22float2(h[3]);
        a[0] += f0.x; a[1] += f0.y;
        a[2] += f1.x; a[3] += f1.y;
        a[4] += f2.x; a[5] += f2.y;
        a[6] += f3.x; a[7] += f3.y;

        i += 8;
        er = en;
    }

#pragma unroll
    for (int j = 0; j < 8; j++)
        a[j] += __shfl_down_sync(0xffffffffu, a[j], 16);

    if (halfe == 0) {
        uint4 hp = __ldg((const uint4*)(anc16 + (size_t)warp * HDIM) + hl);
        float2 h0 = __half22float2(*(__half2*)&hp.x);
        float2 h1 = __half22float2(*(__half2*)&hp.y);
        float2 h2 = __half22float2(*(__half2*)&hp.z);
        float2 h3 = __half22float2(*(__half2*)&hp.w);
        a[0] += 0.1f * h0.x; a[1] += 0.1f * h0.y;
        a[2] += 0.1f * h1.x; a[3] += 0.1f * h1.y;
        a[4] += 0.1f * h2.x; a[5] += 0.1f * h2.y;
        a[6] += 0.1f * h3.x; a[7] += 0.1f * h3.y;

        if (WRITE) {
            __half2 o0 = __floats2half2_rn(a[0], a[1]);
            __half2 o1 = __floats2half2_rn(a[2], a[3]);
            __half2 o2 = __floats2half2_rn(a[4], a[5]);
            __half2 o3 = __floats2half2_rn(a[6], a[7]);
            uint4 ov = make_uint4(*(unsigned*)&o0, *(unsigned*)&o1,
                                  *(unsigned*)&o2, *(unsigned*)&o3);
            *((uint4*)(dst16 + (size_t)warp * HDIM) + hl) = ov;
        }
        if (FIN) {
            float fw = __ldg(sw + swIdx);
            float4* fp = (float4*)(F + (size_t)warp * HDIM) + hl * 2;
            float4 f0 = fp[0], f1 = fp[1];
            f0.x += fw * a[0]; f0.y += fw * a[1]; f0.z += fw * a[2]; f0.w += fw * a[3];
            f1.x += fw * a[4]; f1.y += fw * a[5]; f1.z += fw * a[6]; f1.w += fw * a[7];
            fp[0] = f0; fp[1] = f1;
        }
    }
}

// ---------------------------------------------------------------------------
// Head: out = relu(bn3(F@W3 + b3)) @ W4 + b4  — one warp per node.
// PDL: pre-sync does ws/deg re-zero + weight smem loads (input data only).
// ---------------------------------------------------------------------------
__global__ void head_kernel(const float* __restrict__ F,
                            const float* __restrict__ W3, const float* __restrict__ b3,
                            const float* __restrict__ g3, const float* __restrict__ be3,
                            const float* __restrict__ m3, const float* __restrict__ v3,
                            const float* __restrict__ W4, const float* __restrict__ b4,
                            float* __restrict__ out,
                            float* __restrict__ ws, int* __restrict__ deg) {
    __shared__ float sW3[HDIM * H2DIM];
    __shared__ float sW4[H2DIM * ODIM];
    __shared__ float sS3[H2DIM], sSh3[H2DIM], sB4[ODIM];
    __shared__ float fr[8][HDIM];
    __shared__ float hid[8][H2DIM];

    int tid = threadIdx.x;
    for (int i = blockIdx.x * blockDim.x + tid; i < NNODES; i += gridDim.x * blockDim.x) {
        ws[i] = 0.f; deg[i] = 0;
    }
    for (int i = tid; i < HDIM * H2DIM; i += blockDim.x) sW3[i] = W3[i];
    for (int i = tid; i < H2DIM * ODIM; i += blockDim.x) sW4[i] = W4[i];
    if (tid < H2DIM) {
        float s = g3[tid] * rsqrtf(v3[tid] + EPS);
        sS3[tid] = s;
        sSh3[tid] = (b3[tid] - m3[tid]) * s + be3[tid];
    }
    if (tid < ODIM) sB4[tid] = b4[tid];

    pdl_wait();
    __syncthreads();

    int warp = tid >> 5, lane = tid & 31;
    int nwarps = blockDim.x >> 5;
    for (int n = blockIdx.x * nwarps + warp; n < NNODES; n += gridDim.x * nwarps) {
        ((float4*)fr[warp])[lane] = ((const float4*)(F + (size_t)n * HDIM))[lane];
        __syncwarp();
#pragma unroll
        for (int hh = 0; hh < 2; hh++) {
            int j = lane + 32 * hh;
            float acc = 0.f;
#pragma unroll 8
            for (int k = 0; k < HDIM; k++) acc += fr[warp][k] * sW3[k * H2DIM + j];
            hid[warp][j] = fmaxf(acc * sS3[j] + sSh3[j], 0.f);
        }
        __syncwarp();
        float acc = sB4[lane];
#pragma unroll 8
        for (int j = 0; j < H2DIM; j++) acc += hid[warp][j] * sW4[j * ODIM + lane];
        out[(size_t)n * ODIM + lane] = acc;
        __syncwarp();
    }
}

// ---------------------------------------------------------------------------
// Launch
// ---------------------------------------------------------------------------
extern "C" void kernel_launch(void* const* d_in, const int* in_sizes, int n_in,
                              void* d_out, int out_size) {
    const float* x   = (const float*)d_in[0];
    const int*   ei  = (const int*)d_in[1];
    const float* ew  = (const float*)d_in[2];
    const float* W1  = (const float*)d_in[3];
    const float* b1  = (const float*)d_in[4];
    const float* g1  = (const float*)d_in[5];
    const float* be1 = (const float*)d_in[6];
    const float* m1  = (const float*)d_in[7];
    const float* v1  = (const float*)d_in[8];
    const float* W2  = (const float*)d_in[9];
    const float* b2  = (const float*)d_in[10];
    const float* g2  = (const float*)d_in[11];
    const float* be2 = (const float*)d_in[12];
    const float* m2  = (const float*)d_in[13];
    const float* v2  = (const float*)d_in[14];
    const float* att = (const float*)d_in[15];
    const float* W3  = (const float*)d_in[16];
    const float* b3  = (const float*)d_in[17];
    const float* g3  = (const float*)d_in[18];
    const float* be3 = (const float*)d_in[19];
    const float* m3  = (const float*)d_in[20];
    const float* v3  = (const float*)d_in[21];
    const float* W4  = (const float*)d_in[22];
    const float* b4  = (const float*)d_in[23];

    const int* row = ei;
    const int* col = ei + NEDGES;

    float *B1, *F, *WS, *SW;
    __half* HB[3];
    int *DEG, *CUR, *OFF;
    unsigned* EDGE;
    cudaGetSymbolAddress((void**)&B1,    gB1);
    cudaGetSymbolAddress((void**)&F,     gFz);
    cudaGetSymbolAddress((void**)&HB[0], gH0);
    cudaGetSymbolAddress((void**)&HB[1], gH1);
    cudaGetSymbolAddress((void**)&HB[2], gH2);
    cudaGetSymbolAddress((void**)&WS,    gWsum);
    cudaGetSymbolAddress((void**)&DEG,   gDeg);
    cudaGetSymbolAddress((void**)&CUR,   gCur);
    cudaGetSymbolAddress((void**)&OFF,   gOff);
    cudaGetSymbolAddress((void**)&EDGE,  gEdge);
    cudaGetSymbolAddress((void**)&SW,    gSw);

    const int propBlocks = (NNODES * 32 + 255) / 256;

    // K1: GEMM1 (tf32 mma, double-buffered) + wsum/deg + softmax
    k1_gemm1_wsum<<<GEMM_BLOCKS + WS_BLOCKS, 256>>>(
        x, W1, b1, g1, be1, m1, v1, B1, row, col, ew, WS, DEG, att, SW);

    // K2: GEMM2 (tf32 mma; fp16 state + F=sw0*hc) + padded degree scan
    k2_gemm2_scan<<<GEMM_BLOCKS + 1, 256>>>(
        B1, W2, b2, g2, be2, m2, v2, HB[0], F, SW, DEG, OFF, CUR);

    // K3: fill CSC + padding
    fill_csc_pad<<<EDGE_BLOCKS + NODE_BLOCKS, 256>>>(
        row, col, ew, WS, DEG, OFF, CUR, EDGE);

    // PDL launch config for gather steps 2..25 and head
    cudaLaunchAttribute pdlAttr[1];
    pdlAttr[0].id = cudaLaunchAttributeProgrammaticStreamSerialization;
    pdlAttr[0].val.programmaticStreamSerializationAllowed = 1;

    cudaLaunchConfig_t cfg = {};
    cfg.gridDim  = dim3(propBlocks);
    cfg.blockDim = dim3(256);
    cfg.dynamicSmemBytes = 0;
    cfg.stream = 0;
    cfg.attrs = pdlAttr;
    cfg.numAttrs = 1;

    // K4..K28: propagation (25 steps, 3 rotating fp16 buffers)
    int anci = 0, curi = 0;
    bool first = true;
    for (int k = 0; k < KHOPS; k++) {
        anci = curi;
        for (int t = 0; t < KHOPS; t++) {
            int dsti = 0;
            for (int d = 0; d < 3; d++)
                if (d != anci && d != curi) dsti = d;
            bool fin  = (t == KHOPS - 1);
            bool last = (fin && k == KHOPS - 1);
            const __half* srcp = HB[curi];
            const __half* ancp = HB[anci];
            __half*       dstp = HB[dsti];
            if (first) {
                // no PDL: previous kernel (fill_csc) writes the edge array
                if (fin)
                    prop_gather_h<true, true><<<propBlocks, 256>>>(
                        srcp, ancp, dstp, OFF, EDGE, F, SW, k + 1);
                else
                    prop_gather_h<false, true><<<propBlocks, 256>>>(
                        srcp, ancp, dstp, OFF, EDGE, (float*)nullptr, SW, 0);
                first = false;
            } else if (last) {
                cudaLaunchKernelEx(&cfg, prop_gather_h<true, false>,
                                   srcp, ancp, dstp, OFF, (const unsigned*)EDGE,
                                   F, (const float*)SW, k + 1);
            } else if (fin) {
                cudaLaunchKernelEx(&cfg, prop_gather_h<true, true>,
                                   srcp, ancp, dstp, OFF, (const unsigned*)EDGE,
                                   F, (const float*)SW, k + 1);
            } else {
                cudaLaunchKernelEx(&cfg, prop_gather_h<false, true>,
                                   srcp, ancp, dstp, OFF, (const unsigned*)EDGE,
                                   (float*)nullptr, (const float*)SW, 0);
            }
            curi = dsti;
        }
    }

    // K29: head (+ trailing ws/deg re-zero), PDL-overlapped with last gather
    cudaLaunchConfig_t hcfg = cfg;
    hcfg.gridDim = dim3(1184);
    cudaLaunchKernelEx(&hcfg, head_kernel,
                       (const float*)F, W3, b3, g3, be3, m3, v3, W4, b4,
                       (float*)d_out, WS, DEG);
}

// round 16
// speedup vs baseline: 1.0084x; 1.0084x over previous
#include <cuda_runtime.h>
#include <cuda_fp16.h>
#include <cuda_bf16.h>

// Problem constants
#define NNODES 50000
#define NEDGES 800000
#define IN_DIM 256
#define HDIM   128
#define H2DIM  64
#define ODIM   32
#define KHOPS  5
#define EPS    1e-5f

#define GEMM_BLOCKS ((NNODES + 63) / 64)   // 782
#define WS_BLOCKS   160                    // extra blocks in K1 for wsum/deg
#define PADCAP      (NEDGES + 8 * NNODES + 16)  // padded edge capacity (+prefetch overrun)

// ---------------------------------------------------------------------------
// Scratch (device globals; zero-initialized at module load).
// gWsum/gDeg re-zeroed at END of every launch (head_kernel) for graph replay.
// ---------------------------------------------------------------------------
__device__ float    gB1[NNODES * HDIM];    // GEMM1 output
__device__ float    gFz[NNODES * HDIM];    // fused accumulator
__device__ __half   gH0[NNODES * HDIM];    // fp16 state buffers (rotating)
__device__ __half   gH1[NNODES * HDIM];
__device__ __half   gH2[NNODES * HDIM];
__device__ float    gWsum[NNODES];
__device__ int      gDeg[NNODES];
__device__ int      gCur[NNODES];
__device__ int      gOff[NNODES + 1];
__device__ unsigned gEdge[PADCAP];         // {u16 src | fp16 weight << 16}
__device__ float    gSw[8];

// ---------------------------------------------------------------------------
// PDL primitives
// ---------------------------------------------------------------------------
__device__ __forceinline__ void pdl_wait()   { asm volatile("griddepcontrol.wait;" ::: "memory"); }
__device__ __forceinline__ void pdl_launch() { asm volatile("griddepcontrol.launch_dependents;"); }

// ---------------------------------------------------------------------------
// tf32 mma.sync m16n8k8 (fp32 bits passed directly; HW truncates to tf32)
// ---------------------------------------------------------------------------
__device__ __forceinline__ void mma_tf32(float* d, const float* a, const float* b) {
    asm volatile(
        "mma.sync.aligned.m16n8k8.row.col.f32.tf32.tf32.f32 "
        "{%0,%1,%2,%3}, {%4,%5,%6,%7}, {%8,%9}, {%0,%1,%2,%3};\n"
        : "+f"(d[0]), "+f"(d[1]), "+f"(d[2]), "+f"(d[3])
        : "r"(__float_as_uint(a[0])), "r"(__float_as_uint(a[1])),
          "r"(__float_as_uint(a[2])), "r"(__float_as_uint(a[3])),
          "r"(__float_as_uint(b[0])), "r"(__float_as_uint(b[1])));
}

// ---------------------------------------------------------------------------
// Tensor-core GEMM body: 64x128 block tile, 8 warps in 2x4 grid, 32x32/warp.
// Register-staged double buffering. If PDLW: W/bn-param loads happen before
// the grid-dependency wait (they read only kernel inputs); A loads after.
// ---------------------------------------------------------------------------
template <int KDIM, bool RES, bool FUSEP, bool PDLW>
__device__ __forceinline__ void gemm_body(
    int bx,
    const float* __restrict__ A,
    const float* __restrict__ W,
    const float* __restrict__ bias,
    const float* __restrict__ g,
    const float* __restrict__ be,
    const float* __restrict__ m,
    const float* __restrict__ v,
    const float* __restrict__ ident,
    float* __restrict__ out32,
    __half* __restrict__ out16,
    float* __restrict__ F,
    const float* __restrict__ sw, int M) {
    __shared__ float As[64][17];
    __shared__ float Bs[16][136];
    __shared__ float sS[HDIM], sSh[HDIM], sBB[HDIM];

    const int tid = threadIdx.x;
    const int rowBase = bx * 64;
    const int wid = tid >> 5, lane = tid & 31;
    const int warpM = wid >> 2, warpN = wid & 3;
    const int gg = lane >> 2, tig = lane & 3;

    if (tid < HDIM) {
        float s = g[tid] * rsqrtf(v[tid] + EPS);
        sS[tid] = s;
        sSh[tid] = be[tid] - m[tid] * s;
        sBB[tid] = bias[tid];
    }

    float acc[2][4][4];
#pragma unroll
    for (int mt = 0; mt < 2; mt++)
#pragma unroll
        for (int nt = 0; nt < 4; nt++)
#pragma unroll
            for (int j = 0; j < 4; j++) acc[mt][nt][j] = 0.f;

    const int ar = tid >> 2, ac4 = tid & 3;
    const int wr0 = tid >> 5, wc0 = tid & 31;
    const int wr1 = (tid + 256) >> 5, wc1 = tid & 31;
    float4 nA, nW0, nW1;

    // W prologue (input-only; safe pre-wait)
    nW0 = *(const float4*)(W + (size_t)wr0 * HDIM + wc0 * 4);
    nW1 = *(const float4*)(W + (size_t)wr1 * HDIM + wc1 * 4);

    if (PDLW) pdl_wait();   // A (predecessor output) is only touched below

    nA = make_float4(0.f, 0.f, 0.f, 0.f);
    if (rowBase + ar < M)
        nA = *(const float4*)(A + (size_t)(rowBase + ar) * KDIM + ac4 * 4);

    for (int k0 = 0; k0 < KDIM; k0 += 16) {
        As[ar][ac4 * 4 + 0] = nA.x; As[ar][ac4 * 4 + 1] = nA.y;
        As[ar][ac4 * 4 + 2] = nA.z; As[ar][ac4 * 4 + 3] = nA.w;
        *(float4*)&Bs[wr0][wc0 * 4] = nW0;
        *(float4*)&Bs[wr1][wc1 * 4] = nW1;
        __syncthreads();

        if (k0 + 16 < KDIM) {
            nA = make_float4(0.f, 0.f, 0.f, 0.f);
            if (rowBase + ar < M)
                nA = *(const float4*)(A + (size_t)(rowBase + ar) * KDIM + (k0 + 16) + ac4 * 4);
            nW0 = *(const float4*)(W + (size_t)(k0 + 16 + wr0) * HDIM + wc0 * 4);
            nW1 = *(const float4*)(W + (size_t)(k0 + 16 + wr1) * HDIM + wc1 * 4);
        }

#pragma unroll
        for (int kk = 0; kk < 16; kk += 8) {
            float afr[2][4], bfr[4][2];
#pragma unroll
            for (int mt = 0; mt < 2; mt++) {
                int r0 = warpM * 32 + mt * 16 + gg;
                afr[mt][0] = As[r0][kk + tig];
                afr[mt][1] = As[r0 + 8][kk + tig];
                afr[mt][2] = As[r0][kk + tig + 4];
                afr[mt][3] = As[r0 + 8][kk + tig + 4];
            }
#pragma unroll
            for (int nt = 0; nt < 4; nt++) {
                int c0 = warpN * 32 + nt * 8 + gg;
                bfr[nt][0] = Bs[kk + tig][c0];
                bfr[nt][1] = Bs[kk + tig + 4][c0];
            }
#pragma unroll
            for (int mt = 0; mt < 2; mt++)
#pragma unroll
                for (int nt = 0; nt < 4; nt++)
                    mma_tf32(acc[mt][nt], afr[mt], bfr[nt]);
        }
        __syncthreads();
    }

    float fw = FUSEP ? __ldg(sw) : 0.f;

#pragma unroll
    for (int mt = 0; mt < 2; mt++) {
#pragma unroll
        for (int half = 0; half < 2; half++) {
            int rr = rowBase + warpM * 32 + mt * 16 + gg + half * 8;
            if (rr < M) {
#pragma unroll
                for (int nt = 0; nt < 4; nt++) {
                    int c = warpN * 32 + nt * 8 + 2 * tig;
                    float d0 = acc[mt][nt][half * 2 + 0];
                    float d1 = acc[mt][nt][half * 2 + 1];
                    float o0 = fmaxf((d0 + sBB[c]) * sS[c] + sSh[c], 0.f);
                    float o1 = fmaxf((d1 + sBB[c + 1]) * sS[c + 1] + sSh[c + 1], 0.f);
                    if (RES) {
                        float2 r4 = *(const float2*)(ident + (size_t)rr * HDIM + c);
                        o0 += r4.x; o1 += r4.y;
                    }
                    if (FUSEP) {
                        __half2 h = __floats2half2_rn(o0, o1);
                        *(unsigned*)(out16 + (size_t)rr * HDIM + c) = *(unsigned*)&h;
                        float2 f = make_float2(fw * o0, fw * o1);
                        *(float2*)(F + (size_t)rr * HDIM + c) = f;
                    } else {
                        *(float2*)(out32 + (size_t)rr * HDIM + c) = make_float2(o0, o1);
                    }
                }
            }
        }
    }
}

// ---------------------------------------------------------------------------
// K1: GEMM1 + (tail blocks) wsum/deg accumulation + softmax(att)
// Signals launch_dependents so K2's input-only prologue can start early.
// ---------------------------------------------------------------------------
__global__ void k1_gemm1_wsum(const float* __restrict__ x,
                              const float* __restrict__ W1,
                              const float* __restrict__ b1,
                              const float* __restrict__ g1,
                              const float* __restrict__ be1,
                              const float* __restrict__ m1,
                              const float* __restrict__ v1,
                              float* __restrict__ out32,
                              const int* __restrict__ row,
                              const int* __restrict__ col,
                              const float* __restrict__ ew,
                              float* __restrict__ ws,
                              int* __restrict__ deg,
                              const float* __restrict__ att,
                              float* __restrict__ sw) {
    pdl_launch();
    int bx = blockIdx.x;
    if (bx < GEMM_BLOCKS) {
        gemm_body<IN_DIM, false, false, false>(bx, x, W1, b1, g1, be1, m1, v1,
                                               nullptr, out32, nullptr, nullptr, nullptr, NNODES);
        return;
    }
    int ebx = bx - GEMM_BLOCKS;
    for (int i = ebx * 256 + threadIdx.x; i < NEDGES; i += WS_BLOCKS * 256) {
        atomicAdd(&ws[row[i]], ew[i]);
        atomicAdd(&deg[col[i]], 1);
    }
    if (ebx == WS_BLOCKS - 1 && threadIdx.x == 0) {
        float mx = -1e30f;
        for (int i = 0; i < KHOPS + 1; i++) mx = fmaxf(mx, att[i]);
        float e[KHOPS + 1], sum = 0.f;
        for (int i = 0; i < KHOPS + 1; i++) { e[i] = expf(att[i] - mx); sum += e[i]; }
        for (int i = 0; i < KHOPS + 1; i++) sw[i] = e[i] / sum;
    }
}

// ---------------------------------------------------------------------------
// K2: GEMM2 (+ fp16 state + F init) + (1 tail block) PADDED offset scan
// PDL: W2/bn prologue pre-wait; signals dependents at entry.
// ---------------------------------------------------------------------------
__global__ void k2_gemm2_scan(const float* __restrict__ h1,
                              const float* __restrict__ W2,
                              const float* __restrict__ b2,
                              const float* __restrict__ g2,
                              const float* __restrict__ be2,
                              const float* __restrict__ m2,
                              const float* __restrict__ v2,
                              __half* __restrict__ out16,
                              float* __restrict__ F,
                              const float* __restrict__ sw,
                              const int* __restrict__ deg,
                              int* __restrict__ off,
                              int* __restrict__ cursor) {
    pdl_launch();
    int bx = blockIdx.x;
    if (bx < GEMM_BLOCKS) {
        gemm_body<HDIM, true, true, true>(bx, h1, W2, b2, g2, be2, m2, v2,
                                          h1, nullptr, out16, F, sw, NNODES);
        return;
    }
    pdl_wait();   // deg written by K1
    __shared__ int partial[256];
    const int CH = (NNODES + 255) / 256;   // 196
    int tid = threadIdx.x;
    int start = tid * CH;
    int sum = 0;
    for (int j = 0; j < CH; j++) {
        int idx = start + j;
        if (idx < NNODES) sum += (deg[idx] + 7) & ~7;
    }
    partial[tid] = sum;
    __syncthreads();
    for (int d = 1; d < 256; d <<= 1) {
        int t = (tid >= d) ? partial[tid - d] : 0;
        __syncthreads();
        partial[tid] += t;
        __syncthreads();
    }
    int run = (tid == 0) ? 0 : partial[tid - 1];
    for (int j = 0; j < CH; j++) {
        int idx = start + j;
        if (idx < NNODES) {
            off[idx] = run;
            cursor[idx] = run;
            run += (deg[idx] + 7) & ~7;
        }
    }
    if (tid == 255) off[NNODES] = partial[255];
}

// ---------------------------------------------------------------------------
// K3: fill CSC (edge blocks) + pad fill (node tail blocks).
// PDL: edge blocks pre-load row/col/ew/ws (K1 outputs, complete since K1->K2
// was stream-ordered) and compute the packed record BEFORE waiting; only the
// cursor atomic + store (K2 outputs) come after the wait.
// Record: bits[0:16) = src node id, bits[16:32) = fp16 normalized weight.
// ---------------------------------------------------------------------------
#define EDGE_BLOCKS ((NEDGES + 255) / 256)
#define NODE_BLOCKS ((NNODES + 255) / 256)

__global__ void fill_csc_pad(const int* __restrict__ row,
                             const int* __restrict__ col,
                             const float* __restrict__ w,
                             const float* __restrict__ ws,
                             const int* __restrict__ deg,
                             const int* __restrict__ off,
                             int* __restrict__ cursor,
                             unsigned* __restrict__ edge) {
    pdl_launch();
    int bx = blockIdx.x;
    if (bx < EDGE_BLOCKS) {
        int i = bx * 256 + threadIdx.x;
        int c = 0;
        unsigned rec = 0u;
        bool act = (i < NEDGES);
        if (act) {
            int r = row[i];
            c = col[i];
            float wn = 0.9f * w[i] / fmaxf(ws[r], 1.0f);
            unsigned hw = (unsigned)__half_as_ushort(__float2half_rn(wn));
            rec = (unsigned)r | (hw << 16);
        }
        pdl_wait();   // cursor written by K2
        if (act) {
            int pos = atomicAdd(&cursor[c], 1);
            edge[pos] = rec;
        }
        return;
    }
    pdl_wait();       // deg/off written by K1/K2
    int n = (bx - EDGE_BLOCKS) * 256 + threadIdx.x;
    if (n < NNODES) {
        int d = deg[n];
        int s = off[n] + d;
        int e = off[n] + ((d + 7) & ~7);
        for (int p = s; p < e; p++) edge[p] = 0u;   // src 0, weight 0
    }
}

// ---------------------------------------------------------------------------
// Propagation gather — half-warp owns 4 contiguous edges per trip (one
// LDG.128 fetches all 4 records), LDG.128 rows, padded, fp32 accumulate,
// unclamped next-trip prefetch, PDL pre-sync edge/offset loading.
// Row byte-address extraction: single PRMT.
// ---------------------------------------------------------------------------
__device__ __forceinline__ void acc8(float* a, uint4 p, float wgt) {
    float2 t0 = __half22float2(*(__half2*)&p.x);
    float2 t1 = __half22float2(*(__half2*)&p.y);
    float2 t2 = __half22float2(*(__half2*)&p.z);
    float2 t3 = __half22float2(*(__half2*)&p.w);
    a[0] += wgt * t0.x; a[1] += wgt * t0.y;
    a[2] += wgt * t1.x; a[3] += wgt * t1.y;
    a[4] += wgt * t2.x; a[5] += wgt * t2.y;
    a[6] += wgt * t3.x; a[7] += wgt * t3.y;
}

// (u & 0xFFFF) << 8 as a single PRMT
__device__ __forceinline__ unsigned addr8(unsigned u) { return __byte_perm(u, 0, 0x4104); }
__device__ __forceinline__ float edge_w(unsigned r) {
    return __half2float(__ushort_as_half((unsigned short)(r >> 16)));
}

template <bool FIN, bool WRITE>
__global__ void __launch_bounds__(256, 6)
prop_gather_h(const __half* __restrict__ src16,
              const __half* __restrict__ anc16,
              __half* __restrict__ dst16,
              const int* __restrict__ off,
              const unsigned* __restrict__ edge,
              float* __restrict__ F,
              const float* __restrict__ sw, int swIdx) {
    int warp = (blockIdx.x * blockDim.x + threadIdx.x) >> 5;
    int lane = threadIdx.x & 31;
    int halfe = lane >> 4;    // which 4-edge group of the trip
    int hl    = lane & 15;    // feature chunk within the row (8 fp16)

    // ---- pre-sync: offsets + first edge records (stable across steps) ----
    int s = 0, e = 0;
    uint4 er = make_uint4(0u, 0u, 0u, 0u);
    if (warp < NNODES) {
        s = __ldg(off + warp);
        e = __ldg(off + warp + 1);   // e - s multiple of 8
        er = __ldg((const uint4*)(edge + s + halfe * 4));
    }

    pdl_wait();
    pdl_launch();

    if (warp >= NNODES) return;

    const char* rowBase = (const char*)src16 + (hl << 4);

    float a[8];
#pragma unroll
    for (int j = 0; j < 8; j++) a[j] = 0.f;

    for (int i = s + halfe * 4; i < e; ) {
        uint4 en = __ldg((const uint4*)(edge + i + 8));  // unclamped (padded)

        uint4 p0 = __ldg((const uint4*)(rowBase + addr8(er.x)));
        uint4 p1 = __ldg((const uint4*)(rowBase + addr8(er.y)));
        uint4 p2 = __ldg((const uint4*)(rowBase + addr8(er.z)));
        uint4 p3 = __ldg((const uint4*)(rowBase + addr8(er.w)));
        acc8(a, p0, edge_w(er.x));
        acc8(a, p1, edge_w(er.y));
        acc8(a, p2, edge_w(er.z));
        acc8(a, p3, edge_w(er.w));

        i += 8;
        er = en;
    }

#pragma unroll
    for (int j = 0; j < 8; j++)
        a[j] += __shfl_down_sync(0xffffffffu, a[j], 16);

    if (halfe == 0) {
        uint4 hp = __ldg((const uint4*)(anc16 + (size_t)warp * HDIM) + hl);
        float2 h0 = __half22float2(*(__half2*)&hp.x);
        float2 h1 = __half22float2(*(__half2*)&hp.y);
        float2 h2 = __half22float2(*(__half2*)&hp.z);
        float2 h3 = __half22float2(*(__half2*)&hp.w);
        a[0] += 0.1f * h0.x; a[1] += 0.1f * h0.y;
        a[2] += 0.1f * h1.x; a[3] += 0.1f * h1.y;
        a[4] += 0.1f * h2.x; a[5] += 0.1f * h2.y;
        a[6] += 0.1f * h3.x; a[7] += 0.1f * h3.y;

        if (WRITE) {
            __half2 o0 = __floats2half2_rn(a[0], a[1]);
            __half2 o1 = __floats2half2_rn(a[2], a[3]);
            __half2 o2 = __floats2half2_rn(a[4], a[5]);
            __half2 o3 = __floats2half2_rn(a[6], a[7]);
            uint4 ov = make_uint4(*(unsigned*)&o0, *(unsigned*)&o1,
                                  *(unsigned*)&o2, *(unsigned*)&o3);
            *((uint4*)(dst16 + (size_t)warp * HDIM) + hl) = ov;
        }
        if (FIN) {
            float fw = __ldg(sw + swIdx);
            float4* fp = (float4*)(F + (size_t)warp * HDIM) + hl * 2;
            float4 f0 = fp[0], f1 = fp[1];
            f0.x += fw * a[0]; f0.y += fw * a[1]; f0.z += fw * a[2]; f0.w += fw * a[3];
            f1.x += fw * a[4]; f1.y += fw * a[5]; f1.z += fw * a[6]; f1.w += fw * a[7];
            fp[0] = f0; fp[1] = f1;
        }
    }
}

// ---------------------------------------------------------------------------
// Head: out = relu(bn3(F@W3 + b3)) @ W4 + b4  — one warp per node.
// PDL: pre-sync does ws/deg re-zero + weight smem loads (input data only).
// ---------------------------------------------------------------------------
__global__ void head_kernel(const float* __restrict__ F,
                            const float* __restrict__ W3, const float* __restrict__ b3,
                            const float* __restrict__ g3, const float* __restrict__ be3,
                            const float* __restrict__ m3, const float* __restrict__ v3,
                            const float* __restrict__ W4, const float* __restrict__ b4,
                            float* __restrict__ out,
                            float* __restrict__ ws, int* __restrict__ deg) {
    __shared__ float sW3[HDIM * H2DIM];
    __shared__ float sW4[H2DIM * ODIM];
    __shared__ float sS3[H2DIM], sSh3[H2DIM], sB4[ODIM];
    __shared__ float fr[8][HDIM];
    __shared__ float hid[8][H2DIM];

    int tid = threadIdx.x;
    for (int i = blockIdx.x * blockDim.x + tid; i < NNODES; i += gridDim.x * blockDim.x) {
        ws[i] = 0.f; deg[i] = 0;
    }
    for (int i = tid; i < HDIM * H2DIM; i += blockDim.x) sW3[i] = W3[i];
    for (int i = tid; i < H2DIM * ODIM; i += blockDim.x) sW4[i] = W4[i];
    if (tid < H2DIM) {
        float s = g3[tid] * rsqrtf(v3[tid] + EPS);
        sS3[tid] = s;
        sSh3[tid] = (b3[tid] - m3[tid]) * s + be3[tid];
    }
    if (tid < ODIM) sB4[tid] = b4[tid];

    pdl_wait();
    __syncthreads();

    int warp = tid >> 5, lane = tid & 31;
    int nwarps = blockDim.x >> 5;
    for (int n = blockIdx.x * nwarps + warp; n < NNODES; n += gridDim.x * nwarps) {
        ((float4*)fr[warp])[lane] = ((const float4*)(F + (size_t)n * HDIM))[lane];
        __syncwarp();
#pragma unroll
        for (int hh = 0; hh < 2; hh++) {
            int j = lane + 32 * hh;
            float acc = 0.f;
#pragma unroll 8
            for (int k = 0; k < HDIM; k++) acc += fr[warp][k] * sW3[k * H2DIM + j];
            hid[warp][j] = fmaxf(acc * sS3[j] + sSh3[j], 0.f);
        }
        __syncwarp();
        float acc = sB4[lane];
#pragma unroll 8
        for (int j = 0; j < H2DIM; j++) acc += hid[warp][j] * sW4[j * ODIM + lane];
        out[(size_t)n * ODIM + lane] = acc;
        __syncwarp();
    }
}

// ---------------------------------------------------------------------------
// Launch
// ---------------------------------------------------------------------------
extern "C" void kernel_launch(void* const* d_in, const int* in_sizes, int n_in,
                              void* d_out, int out_size) {
    const float* x   = (const float*)d_in[0];
    const int*   ei  = (const int*)d_in[1];
    const float* ew  = (const float*)d_in[2];
    const float* W1  = (const float*)d_in[3];
    const float* b1  = (const float*)d_in[4];
    const float* g1  = (const float*)d_in[5];
    const float* be1 = (const float*)d_in[6];
    const float* m1  = (const float*)d_in[7];
    const float* v1  = (const float*)d_in[8];
    const float* W2  = (const float*)d_in[9];
    const float* b2  = (const float*)d_in[10];
    const float* g2  = (const float*)d_in[11];
    const float* be2 = (const float*)d_in[12];
    const float* m2  = (const float*)d_in[13];
    const float* v2  = (const float*)d_in[14];
    const float* att = (const float*)d_in[15];
    const float* W3  = (const float*)d_in[16];
    const float* b3  = (const float*)d_in[17];
    const float* g3  = (const float*)d_in[18];
    const float* be3 = (const float*)d_in[19];
    const float* m3  = (const float*)d_in[20];
    const float* v3  = (const float*)d_in[21];
    const float* W4  = (const float*)d_in[22];
    const float* b4  = (const float*)d_in[23];

    const int* row = ei;
    const int* col = ei + NEDGES;

    float *B1, *F, *WS, *SW;
    __half* HB[3];
    int *DEG, *CUR, *OFF;
    unsigned* EDGE;
    cudaGetSymbolAddress((void**)&B1,    gB1);
    cudaGetSymbolAddress((void**)&F,     gFz);
    cudaGetSymbolAddress((void**)&HB[0], gH0);
    cudaGetSymbolAddress((void**)&HB[1], gH1);
    cudaGetSymbolAddress((void**)&HB[2], gH2);
    cudaGetSymbolAddress((void**)&WS,    gWsum);
    cudaGetSymbolAddress((void**)&DEG,   gDeg);
    cudaGetSymbolAddress((void**)&CUR,   gCur);
    cudaGetSymbolAddress((void**)&OFF,   gOff);
    cudaGetSymbolAddress((void**)&EDGE,  gEdge);
    cudaGetSymbolAddress((void**)&SW,    gSw);

    const int propBlocks = (NNODES * 32 + 255) / 256;

    cudaLaunchAttribute pdlAttr[1];
    pdlAttr[0].id = cudaLaunchAttributeProgrammaticStreamSerialization;
    pdlAttr[0].val.programmaticStreamSerializationAllowed = 1;

    // K1: GEMM1 (tf32 mma, double-buffered) + wsum/deg + softmax
    k1_gemm1_wsum<<<GEMM_BLOCKS + WS_BLOCKS, 256>>>(
        x, W1, b1, g1, be1, m1, v1, B1, row, col, ew, WS, DEG, att, SW);

    // K2: GEMM2 (PDL: W2 prologue pre-wait) + padded degree scan
    {
        cudaLaunchConfig_t c2 = {};
        c2.gridDim  = dim3(GEMM_BLOCKS + 1);
        c2.blockDim = dim3(256);
        c2.stream = 0;
        c2.attrs = pdlAttr;
        c2.numAttrs = 1;
        cudaLaunchKernelEx(&c2, k2_gemm2_scan,
                           (const float*)B1, W2, b2, g2, be2, m2, v2,
                           (__half*)HB[0], F, (const float*)SW,
                           (const int*)DEG, OFF, CUR);
    }

    // K3: fill CSC + padding (PDL: edge record computation pre-wait)
    {
        cudaLaunchConfig_t c3 = {};
        c3.gridDim  = dim3(EDGE_BLOCKS + NODE_BLOCKS);
        c3.blockDim = dim3(256);
        c3.stream = 0;
        c3.attrs = pdlAttr;
        c3.numAttrs = 1;
        cudaLaunchKernelEx(&c3, fill_csc_pad,
                           row, col, ew, (const float*)WS, (const int*)DEG,
                           (const int*)OFF, CUR, EDGE);
    }

    cudaLaunchConfig_t cfg = {};
    cfg.gridDim  = dim3(propBlocks);
    cfg.blockDim = dim3(256);
    cfg.dynamicSmemBytes = 0;
    cfg.stream = 0;
    cfg.attrs = pdlAttr;
    cfg.numAttrs = 1;

    // K4..K28: propagation (25 steps, 3 rotating fp16 buffers)
    int anci = 0, curi = 0;
    bool first = true;
    for (int k = 0; k < KHOPS; k++) {
        anci = curi;
        for (int t = 0; t < KHOPS; t++) {
            int dsti = 0;
            for (int d = 0; d < 3; d++)
                if (d != anci && d != curi) dsti = d;
            bool fin  = (t == KHOPS - 1);
            bool last = (fin && k == KHOPS - 1);
            const __half* srcp = HB[curi];
            const __half* ancp = HB[anci];
            __half*       dstp = HB[dsti];
            if (first) {
                // no PDL: previous kernel (fill_csc) writes the edge array
                if (fin)
                    prop_gather_h<true, true><<<propBlocks, 256>>>(
                        srcp, ancp, dstp, OFF, EDGE, F, SW, k + 1);
                else
                    prop_gather_h<false, true><<<propBlocks, 256>>>(
                        srcp, ancp, dstp, OFF, EDGE, (float*)nullptr, SW, 0);
                first = false;
            } else if (last) {
                cudaLaunchKernelEx(&cfg, prop_gather_h<true, false>,
                                   srcp, ancp, dstp, OFF, (const unsigned*)EDGE,
                                   F, (const float*)SW, k + 1);
            } else if (fin) {
                cudaLaunchKernelEx(&cfg, prop_gather_h<true, true>,
                                   srcp, ancp, dstp, OFF, (const unsigned*)EDGE,
                                   F, (const float*)SW, k + 1);
            } else {
                cudaLaunchKernelEx(&cfg, prop_gather_h<false, true>,
                                   srcp, ancp, dstp, OFF, (const unsigned*)EDGE,
                                   (float*)nullptr, (const float*)SW, 0);
            }
            curi = dsti;
        }
    }

    // K29: head (+ trailing ws/deg re-zero), PDL-overlapped with last gather
    cudaLaunchConfig_t hcfg = cfg;
    hcfg.gridDim = dim3(1184);
    cudaLaunchKernelEx(&hcfg, head_kernel,
                       (const float*)F, W3, b3, g3, be3, m3, v3, W4, b4,
                       (float*)d_out, WS, DEG);
}